// round 2
// baseline (speedup 1.0000x reference)
#include <cuda_runtime.h>
#include <math.h>

#define HH 512
#define BB 64
#define SS 400
#define VV 50000
#define VS 50400

typedef unsigned long long ull;

__device__ __align__(16) float g_WhT[HH * HH];
__device__ __align__(16) float g_WsT[HH * HH];
__device__ __align__(16) float g_giT[3 * HH * BB];
__device__ __align__(16) float g_ghT[3 * HH * BB];
__device__ __align__(16) float g_h[BB * HH];
__device__ __align__(16) float g_x2pT[HH * BB];
__device__ __align__(16) float g_spart[8 * SS * BB];
__device__ __align__(16) float g_attn[SS * BB];
__device__ __align__(16) float g_gs[BB * 2 * HH];
__device__ __align__(16) float g_p[BB];

__device__ __forceinline__ ull dup2(float x) {
    ull d; unsigned r = __float_as_uint(x);
    asm("mov.b64 %0, {%1,%2};" : "=l"(d) : "r"(r), "r"(r));
    return d;
}
__device__ __forceinline__ ull fma2(ull a, ull b, ull c) {
    ull d;
    asm("fma.rn.f32x2 %0, %1, %2, %3;" : "=l"(d) : "l"(a), "l"(b), "l"(c));
    return d;
}
__device__ __forceinline__ float2 unpk(ull v) {
    unsigned lo, hi;
    asm("mov.b64 {%0,%1}, %2;" : "=r"(lo), "=r"(hi) : "l"(v));
    return make_float2(__uint_as_float(lo), __uint_as_float(hi));
}

// NT GEMM: C[m][n] = sum_k A[m][k]*Bm[n][k]. BM=128, BN=64, BK=16, 128 thr.
// EPI0: out[m*64+n] = acc + bias[m]
// EPI1: out[by*25600+m] = sum_n tanh(acc + x2pT[n][b]) * v[n]   (partials)
// EPI2: out[n*VS+m] = p[n] * selu(acc + bias[m])
template <int EPI>
__global__ void __launch_bounds__(128)
gemm_nt(const float* __restrict__ A, const float* __restrict__ Bm,
        const float* __restrict__ bias, float* __restrict__ out,
        int M, int K,
        const float* __restrict__ ex2p, const float* __restrict__ ev,
        const float* __restrict__ ep)
{
    __shared__ float sh[8320];
    float* sA = sh;                      // [16][128]
    float* sB = sh + 2048;               // [16][64]
    float* x2ps = sh + 3072;             // [64][64] (EPI1)
    float* vs = sh + 7168;               // [64]     (EPI1)
    float* red = sh + 7232;              // [8][128] (EPI1)
    float* cst = sh;                     // [64][128](EPI2)
    float* ps = sh + 8192;               // [64]     (EPI2)

    const int tid = threadIdx.x;
    const int tmq = tid & 15, tnq = tid >> 4;
    const int mBase = blockIdx.x * 128, nBase = blockIdx.y * 64;

    if (EPI == 1) {
        const float4* src = (const float4*)(ex2p + (size_t)nBase * 64);
        float4* dst = (float4*)x2ps;
        #pragma unroll
        for (int i = 0; i < 8; i++) dst[tid + 128 * i] = src[tid + 128 * i];
        if (tid < 64) vs[tid] = ev[nBase + tid];
    }
    if (EPI == 2 && tid < 64) ps[tid] = ep[tid];

    ull acc[8][4];
    #pragma unroll
    for (int i = 0; i < 8; i++)
        #pragma unroll
        for (int j = 0; j < 4; j++) acc[i][j] = 0ull;

    for (int k0 = 0; k0 < K; k0 += 16) {
        __syncthreads();
        #pragma unroll
        for (int i = 0; i < 4; i++) {
            int q = tid + 128 * i, r = q >> 2, c4 = q & 3;
            int m = mBase + r;
            float4 va = make_float4(0.f, 0.f, 0.f, 0.f);
            if (m < M) va = *(const float4*)(A + (size_t)m * K + k0 + c4 * 4);
            sA[(c4 * 4 + 0) * 128 + r] = va.x;
            sA[(c4 * 4 + 1) * 128 + r] = va.y;
            sA[(c4 * 4 + 2) * 128 + r] = va.z;
            sA[(c4 * 4 + 3) * 128 + r] = va.w;
        }
        #pragma unroll
        for (int i = 0; i < 2; i++) {
            int q = tid + 128 * i, r = q >> 2, c4 = q & 3;
            float4 vb = *(const float4*)(Bm + (size_t)(nBase + r) * K + k0 + c4 * 4);
            sB[(c4 * 4 + 0) * 64 + r] = vb.x;
            sB[(c4 * 4 + 1) * 64 + r] = vb.y;
            sB[(c4 * 4 + 2) * 64 + r] = vb.z;
            sB[(c4 * 4 + 3) * 64 + r] = vb.w;
        }
        __syncthreads();
        #pragma unroll
        for (int kk = 0; kk < 16; kk++) {
            const float4 a0 = *(const float4*)&sA[kk * 128 + tmq * 4];
            const float4 a1 = *(const float4*)&sA[kk * 128 + 64 + tmq * 4];
            ull ad[8];
            ad[0]=dup2(a0.x); ad[1]=dup2(a0.y); ad[2]=dup2(a0.z); ad[3]=dup2(a0.w);
            ad[4]=dup2(a1.x); ad[5]=dup2(a1.y); ad[6]=dup2(a1.z); ad[7]=dup2(a1.w);
            const ulonglong2 b0 = *(const ulonglong2*)&sB[kk * 64 + tnq * 4];
            const ulonglong2 b1 = *(const ulonglong2*)&sB[kk * 64 + 32 + tnq * 4];
            #pragma unroll
            for (int i = 0; i < 8; i++) {
                acc[i][0] = fma2(ad[i], b0.x, acc[i][0]);
                acc[i][1] = fma2(ad[i], b0.y, acc[i][1]);
                acc[i][2] = fma2(ad[i], b1.x, acc[i][2]);
                acc[i][3] = fma2(ad[i], b1.y, acc[i][3]);
            }
        }
    }
    __syncthreads();

    if (EPI == 0) {
        #pragma unroll
        for (int mi = 0; mi < 8; mi++) {
            int mloc = (mi < 4) ? (tmq * 4 + mi) : (64 + tmq * 4 + mi - 4);
            int m = mBase + mloc;
            if (m < M) {
                float bv = bias ? bias[m] : 0.f;
                #pragma unroll
                for (int nj = 0; nj < 4; nj++) {
                    int nb = (nj < 2) ? (tnq * 4 + nj * 2) : (32 + tnq * 4 + (nj - 2) * 2);
                    float2 c = unpk(acc[mi][nj]);
                    float2 o; o.x = c.x + bv; o.y = c.y + bv;
                    *(float2*)(out + (size_t)m * 64 + nb) = o;
                }
            }
        }
    } else if (EPI == 1) {
        #pragma unroll
        for (int mi = 0; mi < 8; mi++) {
            int mloc = (mi < 4) ? (tmq * 4 + mi) : (64 + tmq * 4 + mi - 4);
            int bcol = mloc & 63;
            float s = 0.f;
            #pragma unroll
            for (int nj = 0; nj < 4; nj++) {
                int nb = (nj < 2) ? (tnq * 4 + nj * 2) : (32 + tnq * 4 + (nj - 2) * 2);
                float2 c = unpk(acc[mi][nj]);
                s += tanhf(c.x + x2ps[nb * 64 + bcol]) * vs[nb];
                s += tanhf(c.y + x2ps[(nb + 1) * 64 + bcol]) * vs[nb + 1];
            }
            red[tnq * 128 + mloc] = s;
        }
        __syncthreads();
        float t = 0.f;
        #pragma unroll
        for (int g = 0; g < 8; g++) t += red[g * 128 + tid];
        out[(size_t)blockIdx.y * (SS * BB) + mBase + tid] = t;
    } else {
        const float SC = 1.0507009873554805f, AL = 1.6732632423543772f;
        #pragma unroll
        for (int mi = 0; mi < 8; mi++) {
            int mloc = (mi < 4) ? (tmq * 4 + mi) : (64 + tmq * 4 + mi - 4);
            int m = mBase + mloc;
            float ob = (m < M) ? bias[m] : 0.f;
            #pragma unroll
            for (int nj = 0; nj < 4; nj++) {
                int nb = (nj < 2) ? (tnq * 4 + nj * 2) : (32 + tnq * 4 + (nj - 2) * 2);
                float2 c = unpk(acc[mi][nj]);
                float v0 = c.x + ob; v0 = SC * (v0 > 0.f ? v0 : AL * expm1f(v0));
                float v1 = c.y + ob; v1 = SC * (v1 > 0.f ? v1 : AL * expm1f(v1));
                cst[nb * 128 + mloc] = v0 * ps[nb];
                cst[(nb + 1) * 128 + mloc] = v1 * ps[nb + 1];
            }
        }
        __syncthreads();
        int mrem = M - mBase; if (mrem > 128) mrem = 128;
        if (tid < mrem) {
            #pragma unroll 4
            for (int n = 0; n < 64; n++)
                out[(size_t)n * VS + mBase + tid] = cst[n * 128 + tid];
        }
    }
}

__global__ void transpose512(const float* __restrict__ in, float* __restrict__ out)
{
    __shared__ float t[32][33];
    int bx = blockIdx.x * 32, by = blockIdx.y * 32;
    int tx = threadIdx.x, ty = threadIdx.y;
    #pragma unroll
    for (int i = 0; i < 32; i += 8)
        t[ty + i][tx] = in[(size_t)(by + ty + i) * 512 + bx + tx];
    __syncthreads();
    #pragma unroll
    for (int i = 0; i < 32; i += 8)
        out[(size_t)(bx + ty + i) * 512 + by + tx] = t[tx][ty + i];
}

__global__ void gru_gates(const float* __restrict__ giT, const float* __restrict__ ghT,
                          const float* __restrict__ h0,
                          float* __restrict__ gh, float* __restrict__ gs,
                          float* __restrict__ dhid)
{
    int idx = blockIdx.x * 256 + threadIdx.x;
    int b = idx & 63, j = idx >> 6;
    float ir = giT[j * 64 + b],           hr = ghT[j * 64 + b];
    float iz = giT[(512 + j) * 64 + b],   hz = ghT[(512 + j) * 64 + b];
    float in_ = giT[(1024 + j) * 64 + b], hn = ghT[(1024 + j) * 64 + b];
    float r = 1.f / (1.f + expf(-(ir + hr)));
    float z = 1.f / (1.f + expf(-(iz + hz)));
    float n = tanhf(in_ + r * hn);
    float h = (1.f - z) * n + z * h0[b * 512 + j];
    gh[b * 512 + j] = h;
    gs[b * 1024 + j] = h;
    dhid[b * 512 + j] = h;
}

__global__ void softmax_col(const float* __restrict__ sp, float* __restrict__ attn,
                            float* __restrict__ dattn)
{
    int b = blockIdx.x, tid = threadIdx.x;
    __shared__ float sv[SS];
    __shared__ float rb[8];
    __shared__ float smax, ssum;
    float mx = -3.4e38f;
    for (int s = tid; s < SS; s += 256) {
        float xv = 0.f;
        #pragma unroll
        for (int q = 0; q < 8; q++) xv += sp[q * (SS * BB) + s * BB + b];
        sv[s] = xv;
        mx = fmaxf(mx, xv);
    }
    #pragma unroll
    for (int o = 16; o; o >>= 1) mx = fmaxf(mx, __shfl_xor_sync(0xffffffffu, mx, o));
    if ((tid & 31) == 0) rb[tid >> 5] = mx;
    __syncthreads();
    if (tid == 0) {
        float m2 = rb[0];
        #pragma unroll
        for (int i = 1; i < 8; i++) m2 = fmaxf(m2, rb[i]);
        smax = m2;
    }
    __syncthreads();
    float sum = 0.f;
    for (int s = tid; s < SS; s += 256) {
        float e = expf(sv[s] - smax);
        sv[s] = e;
        sum += e;
    }
    #pragma unroll
    for (int o = 16; o; o >>= 1) sum += __shfl_xor_sync(0xffffffffu, sum, o);
    if ((tid & 31) == 0) rb[tid >> 5] = sum;
    __syncthreads();
    if (tid == 0) {
        float t = 0.f;
        #pragma unroll
        for (int i = 0; i < 8; i++) t += rb[i];
        ssum = t;
    }
    __syncthreads();
    float inv = 1.f / ssum;
    for (int s = tid; s < SS; s += 256) {
        float a = sv[s] * inv;
        attn[s * BB + b] = a;
        dattn[s * BB + b] = a;
    }
}

__global__ void context_k(const float* __restrict__ attn, const float* __restrict__ enc,
                          float* __restrict__ gs)
{
    int b = blockIdx.x;
    int h = blockIdx.y * 128 + threadIdx.x;
    __shared__ float at[SS];
    for (int s = threadIdx.x; s < SS; s += 128) at[s] = attn[s * BB + b];
    __syncthreads();
    float acc = 0.f;
    const float* p = enc + (size_t)b * 512 + h;
    #pragma unroll 8
    for (int s = 0; s < SS; s++) acc += at[s] * p[(size_t)s * (BB * HH)];
    gs[b * 1024 + 512 + h] = acc;
}

__global__ void pgen_k(const float* __restrict__ gs, const float* __restrict__ x,
                       const float* __restrict__ pWh, const float* __restrict__ pWs,
                       const float* __restrict__ pWx, const float* __restrict__ pWx_b,
                       float* __restrict__ gp, float* __restrict__ dp)
{
    int b = blockIdx.x, tid = threadIdx.x;
    __shared__ float rb[4];
    float a = 0.f;
    for (int j = tid; j < 512; j += 128) {
        a += gs[b * 1024 + 512 + j] * pWh[j]
           + gs[b * 1024 + j] * pWs[j]
           + x[b * 512 + j] * pWx[j];
    }
    #pragma unroll
    for (int o = 16; o; o >>= 1) a += __shfl_xor_sync(0xffffffffu, a, o);
    if ((tid & 31) == 0) rb[tid >> 5] = a;
    __syncthreads();
    if (tid == 0) {
        float t = rb[0] + rb[1] + rb[2] + rb[3];
        float p = 1.f / (1.f + expf(-(t + pWx_b[0])));
        gp[b] = p; dp[b] = p;
    }
}

__global__ void oov_k(const float* __restrict__ attn, const int* __restrict__ mask,
                      const float* __restrict__ gp, float* __restrict__ dout)
{
    int idx = blockIdx.x * 256 + threadIdx.x;
    if (idx >= SS * BB) return;
    int s = idx >> 6, b = idx & 63;
    dout[(size_t)b * VS + VV + s] = (1.f - gp[b]) * attn[idx] * (float)mask[idx];
}

extern "C" void kernel_launch(void* const* d_in, const int* in_sizes, int n_in,
                              void* d_out, int out_size)
{
    const float* x      = (const float*)d_in[0];
    const float* enc    = (const float*)d_in[1];
    const int*   mask   = (const int*)d_in[2];
    const float* h0     = (const float*)d_in[3];
    const float* W_ih   = (const float*)d_in[4];
    const float* W_hh   = (const float*)d_in[5];
    const float* b_ih   = (const float*)d_in[6];
    const float* b_hh   = (const float*)d_in[7];
    const float* out_W  = (const float*)d_in[8];
    const float* out_b  = (const float*)d_in[9];
    const float* v      = (const float*)d_in[10];
    const float* Wh     = (const float*)d_in[11];
    const float* Ws     = (const float*)d_in[12];
    const float* b_attn = (const float*)d_in[13];
    const float* pWh    = (const float*)d_in[14];
    const float* pWs    = (const float*)d_in[15];
    const float* pWx    = (const float*)d_in[16];
    const float* pWx_b  = (const float*)d_in[17];
    float* out = (float*)d_out;

    float *WhT, *WsT, *giT, *ghT, *hb, *x2pT, *spart, *attn, *gs, *pb;
    cudaGetSymbolAddress((void**)&WhT,   g_WhT);
    cudaGetSymbolAddress((void**)&WsT,   g_WsT);
    cudaGetSymbolAddress((void**)&giT,   g_giT);
    cudaGetSymbolAddress((void**)&ghT,   g_ghT);
    cudaGetSymbolAddress((void**)&hb,    g_h);
    cudaGetSymbolAddress((void**)&x2pT,  g_x2pT);
    cudaGetSymbolAddress((void**)&spart, g_spart);
    cudaGetSymbolAddress((void**)&attn,  g_attn);
    cudaGetSymbolAddress((void**)&gs,    g_gs);
    cudaGetSymbolAddress((void**)&pb,    g_p);

    float* dout  = out;
    float* dhid  = out + (size_t)BB * VS;
    float* dp    = dhid + (size_t)BB * HH;
    float* dattn = dp + BB;

    dim3 tb(32, 8);
    transpose512<<<dim3(16, 16), tb>>>(Wh, WhT);
    transpose512<<<dim3(16, 16), tb>>>(Ws, WsT);
    gemm_nt<0><<<dim3(12, 1), 128>>>(W_ih, x, b_ih, giT, 1536, 512,
                                     nullptr, nullptr, nullptr);
    gemm_nt<0><<<dim3(12, 1), 128>>>(W_hh, h0, b_hh, ghT, 1536, 512,
                                     nullptr, nullptr, nullptr);
    gru_gates<<<128, 256>>>(giT, ghT, h0, hb, gs, dhid);
    gemm_nt<0><<<dim3(4, 1), 128>>>(WsT, hb, b_attn, x2pT, 512, 512,
                                    nullptr, nullptr, nullptr);
    gemm_nt<1><<<dim3(200, 8), 128>>>(enc, WhT, nullptr, spart, SS * BB, 512,
                                      x2pT, v, nullptr);
    softmax_col<<<64, 256>>>(spart, attn, dattn);
    context_k<<<dim3(64, 4), 128>>>(attn, enc, gs);
    pgen_k<<<64, 128>>>(gs, x, pWh, pWs, pWx, pWx_b, pb, dp);
    gemm_nt<2><<<dim3(391, 1), 128>>>(out_W, gs, out_b, dout, VV, 2 * HH,
                                      nullptr, nullptr, pb);
    oov_k<<<100, 256>>>(attn, mask, pb, dout);
}

// round 3
// speedup vs baseline: 1.2611x; 1.2611x over previous
#include <cuda_runtime.h>
#include <math.h>

#define HH 512
#define BB 64
#define SS 400
#define VV 50000
#define VS 50400

typedef unsigned long long ull;

// ---------------- scratch ----------------
__device__ __align__(16) float g_gip[4 * 1536 * 64];
__device__ __align__(16) float g_ghp[4 * 1536 * 64];
__device__ __align__(16) float g_x2p[4 * 512 * 64];
__device__ __align__(16) float g_h[BB * HH];
__device__ __align__(16) float g_spart[8 * SS * BB];
__device__ __align__(16) float g_attn[SS * BB];
__device__ __align__(16) float g_gs[BB * 2 * HH];
__device__ __align__(16) float g_p[BB];

// ---------------- f32x2 helpers ----------------
__device__ __forceinline__ ull dup2(float x) {
    ull d; unsigned r = __float_as_uint(x);
    asm("mov.b64 %0, {%1,%2};" : "=l"(d) : "r"(r), "r"(r));
    return d;
}
__device__ __forceinline__ ull fma2(ull a, ull b, ull c) {
    ull d;
    asm("fma.rn.f32x2 %0, %1, %2, %3;" : "=l"(d) : "l"(a), "l"(b), "l"(c));
    return d;
}
__device__ __forceinline__ float2 unpk(ull v) {
    unsigned lo, hi;
    asm("mov.b64 {%0,%1}, %2;" : "=r"(lo), "=r"(hi) : "l"(v));
    return make_float2(__uint_as_float(lo), __uint_as_float(hi));
}

// ============ big NT GEMM, double-buffered ============
// C[m][n] = sum_k A[m][k] * B(n,k). BM=128, BN=64, BK=16, 128 threads.
// TB=false: B row-major [n][k] (stride K). TB=true: B is [k][n] (stride ldb).
// EPI1: out[by*25600+m] = sum_n tanh(acc + x2ps[n][b]) * v[n]  (8 partials)
// EPI2: out[n*VS+m] = p[n] * selu(acc + bias[m])
template <int EPI, bool TB>
__global__ void __launch_bounds__(128)
gemm_nt(const float* __restrict__ A, const float* __restrict__ Bm,
        const float* __restrict__ bias, float* __restrict__ out,
        int M, int K, int ldb,
        const float* __restrict__ xp, const float* __restrict__ ev,
        const float* __restrict__ ep, const float* __restrict__ battn)
{
    __shared__ float sh[11328];   // buf0[0..3072) buf1[3072..6144) extras beyond

    const int tid = threadIdx.x;
    const int tmq = tid & 15, tnq = tid >> 4;
    const int mBase = blockIdx.x * 128, nBase = blockIdx.y * 64;

    if (EPI == 1) {
        // x2ps[n][b] = sum_s x2part[s] + b_attn[n]   at sh+6144 (64x64)
        #pragma unroll
        for (int i = 0; i < 8; i++) {
            int idx4 = tid + 128 * i;
            int n = idx4 >> 4, b4 = idx4 & 15;
            float ba = battn[nBase + n];
            float4 a = make_float4(ba, ba, ba, ba);
            #pragma unroll
            for (int s = 0; s < 4; s++) {
                float4 t = *(const float4*)(xp + (size_t)s * 32768 +
                                            (size_t)(nBase + n) * 64 + b4 * 4);
                a.x += t.x; a.y += t.y; a.z += t.z; a.w += t.w;
            }
            *(float4*)(sh + 6144 + n * 64 + b4 * 4) = a;
        }
        if (tid < 64) sh[10240 + tid] = ev[nBase + tid];
    }
    if (EPI == 2 && tid < 64) sh[8192 + tid] = ep[tid];

    ull acc[8][4];
    #pragma unroll
    for (int i = 0; i < 8; i++)
        #pragma unroll
        for (int j = 0; j < 4; j++) acc[i][j] = 0ull;

    float4 pa[4], pb[2];

    auto loadA = [&](int k0) {
        #pragma unroll
        for (int i = 0; i < 4; i++) {
            int q = tid + 128 * i, r = q >> 2, c4 = q & 3;
            int m = mBase + r;
            pa[i] = (m < M) ? *(const float4*)(A + (size_t)m * K + k0 + c4 * 4)
                            : make_float4(0.f, 0.f, 0.f, 0.f);
        }
    };
    auto loadB = [&](int k0) {
        #pragma unroll
        for (int i = 0; i < 2; i++) {
            int q = tid + 128 * i;
            if (!TB) {
                int r = q >> 2, c4 = q & 3;
                pb[i] = *(const float4*)(Bm + (size_t)(nBase + r) * K + k0 + c4 * 4);
            } else {
                int kk = q >> 4, n4 = q & 15;
                pb[i] = *(const float4*)(Bm + (size_t)(k0 + kk) * ldb + nBase + n4 * 4);
            }
        }
    };
    auto storeT = [&](float* buf) {
        float* sA = buf; float* sB = buf + 2048;
        #pragma unroll
        for (int i = 0; i < 4; i++) {
            int q = tid + 128 * i, r = q >> 2, c4 = q & 3;
            sA[(c4 * 4 + 0) * 128 + r] = pa[i].x;
            sA[(c4 * 4 + 1) * 128 + r] = pa[i].y;
            sA[(c4 * 4 + 2) * 128 + r] = pa[i].z;
            sA[(c4 * 4 + 3) * 128 + r] = pa[i].w;
        }
        #pragma unroll
        for (int i = 0; i < 2; i++) {
            int q = tid + 128 * i;
            if (!TB) {
                int r = q >> 2, c4 = q & 3;
                sB[(c4 * 4 + 0) * 64 + r] = pb[i].x;
                sB[(c4 * 4 + 1) * 64 + r] = pb[i].y;
                sB[(c4 * 4 + 2) * 64 + r] = pb[i].z;
                sB[(c4 * 4 + 3) * 64 + r] = pb[i].w;
            } else {
                int kk = q >> 4, n4 = q & 15;
                *(float4*)&sB[kk * 64 + n4 * 4] = pb[i];
            }
        }
    };

    loadA(0); loadB(0);
    storeT(sh);
    __syncthreads();

    const int T = K >> 4;
    for (int t = 0; t < T; t++) {
        float* cb = sh + (t & 1) * 3072;
        if (t + 1 < T) { loadA((t + 1) << 4); loadB((t + 1) << 4); }
        float* sA = cb; float* sB = cb + 2048;
        #pragma unroll
        for (int kk = 0; kk < 16; kk++) {
            const float4 a0 = *(const float4*)&sA[kk * 128 + tmq * 4];
            const float4 a1 = *(const float4*)&sA[kk * 128 + 64 + tmq * 4];
            ull ad[8];
            ad[0]=dup2(a0.x); ad[1]=dup2(a0.y); ad[2]=dup2(a0.z); ad[3]=dup2(a0.w);
            ad[4]=dup2(a1.x); ad[5]=dup2(a1.y); ad[6]=dup2(a1.z); ad[7]=dup2(a1.w);
            const ulonglong2 b0 = *(const ulonglong2*)&sB[kk * 64 + tnq * 4];
            const ulonglong2 b1 = *(const ulonglong2*)&sB[kk * 64 + 32 + tnq * 4];
            #pragma unroll
            for (int i = 0; i < 8; i++) {
                acc[i][0] = fma2(ad[i], b0.x, acc[i][0]);
                acc[i][1] = fma2(ad[i], b0.y, acc[i][1]);
                acc[i][2] = fma2(ad[i], b1.x, acc[i][2]);
                acc[i][3] = fma2(ad[i], b1.y, acc[i][3]);
            }
        }
        if (t + 1 < T) storeT(sh + ((t + 1) & 1) * 3072);
        __syncthreads();
    }

    if (EPI == 1) {
        float* x2ps = sh + 6144;
        float* vs = sh + 10240;
        float* red = sh + 10304;
        #pragma unroll
        for (int mi = 0; mi < 8; mi++) {
            int mloc = (mi < 4) ? (tmq * 4 + mi) : (64 + tmq * 4 + mi - 4);
            int bcol = mloc & 63;
            float s = 0.f;
            #pragma unroll
            for (int nj = 0; nj < 4; nj++) {
                int nb = (nj < 2) ? (tnq * 4 + nj * 2) : (32 + tnq * 4 + (nj - 2) * 2);
                float2 c = unpk(acc[mi][nj]);
                s += tanhf(c.x + x2ps[nb * 64 + bcol]) * vs[nb];
                s += tanhf(c.y + x2ps[(nb + 1) * 64 + bcol]) * vs[nb + 1];
            }
            red[tnq * 128 + mloc] = s;
        }
        __syncthreads();
        float t = 0.f;
        #pragma unroll
        for (int g = 0; g < 8; g++) t += red[g * 128 + tid];
        out[(size_t)blockIdx.y * (SS * BB) + mBase + tid] = t;
    } else {
        float* cst = sh;
        float* ps = sh + 8192;
        const float SC = 1.0507009873554805f, AL = 1.6732632423543772f;
        #pragma unroll
        for (int mi = 0; mi < 8; mi++) {
            int mloc = (mi < 4) ? (tmq * 4 + mi) : (64 + tmq * 4 + mi - 4);
            int m = mBase + mloc;
            float ob = (m < M) ? bias[m] : 0.f;
            #pragma unroll
            for (int nj = 0; nj < 4; nj++) {
                int nb = (nj < 2) ? (tnq * 4 + nj * 2) : (32 + tnq * 4 + (nj - 2) * 2);
                float2 c = unpk(acc[mi][nj]);
                float v0 = c.x + ob; v0 = SC * (v0 > 0.f ? v0 : AL * expm1f(v0));
                float v1 = c.y + ob; v1 = SC * (v1 > 0.f ? v1 : AL * expm1f(v1));
                cst[nb * 128 + mloc] = v0 * ps[nb];
                cst[(nb + 1) * 128 + mloc] = v1 * ps[nb + 1];
            }
        }
        __syncthreads();
        int mrem = M - mBase; if (mrem > 128) mrem = 128;
        if (tid < mrem) {
            #pragma unroll 4
            for (int n = 0; n < 64; n++)
                out[(size_t)n * VS + mBase + tid] = cst[n * 128 + tid];
        }
    }
}

// ============ small split-K GEMM (K=512, N=64) ============
// grid = (M/64, 4). Each block: 64x64 over a 128-wide K chunk.
// outp[split*(M*64) + m*64 + b] partial sums (reduced by consumer).
// TRANSA=false: A[m][k] row-major (stride 512). TRANSA=true: A[k][m] (stride 512).
template <bool TRANSA>
__global__ void __launch_bounds__(256)
small_gemm(const float* __restrict__ A, const float* __restrict__ B,
           float* __restrict__ outp, int M)
{
    __shared__ float sA[1024], sB[1024];
    const int tid = threadIdx.x;
    const int tmq = tid & 15, tnq = tid >> 4;
    const int mBase = blockIdx.x * 64;
    const int kBase = blockIdx.y * 128;
    float acc[4][4] = {};

    for (int k0 = kBase; k0 < kBase + 128; k0 += 16) {
        __syncthreads();
        if (!TRANSA) {
            int r = tid >> 2, c4 = tid & 3;
            float4 va = *(const float4*)(A + (size_t)(mBase + r) * 512 + k0 + c4 * 4);
            sA[(c4 * 4 + 0) * 64 + r] = va.x;
            sA[(c4 * 4 + 1) * 64 + r] = va.y;
            sA[(c4 * 4 + 2) * 64 + r] = va.z;
            sA[(c4 * 4 + 3) * 64 + r] = va.w;
        } else {
            #pragma unroll
            for (int j = 0; j < 4; j++) {
                int idx = tid + 256 * j;
                int kk = idx >> 6, m = idx & 63;
                sA[kk * 64 + m] = A[(size_t)(k0 + kk) * 512 + mBase + m];
            }
        }
        {
            int r = tid >> 2, c4 = tid & 3;
            float4 vb = *(const float4*)(B + (size_t)r * 512 + k0 + c4 * 4);
            sB[(c4 * 4 + 0) * 64 + r] = vb.x;
            sB[(c4 * 4 + 1) * 64 + r] = vb.y;
            sB[(c4 * 4 + 2) * 64 + r] = vb.z;
            sB[(c4 * 4 + 3) * 64 + r] = vb.w;
        }
        __syncthreads();
        #pragma unroll
        for (int kk = 0; kk < 16; kk++) {
            float4 a = *(const float4*)&sA[kk * 64 + tmq * 4];
            float4 b = *(const float4*)&sB[kk * 64 + tnq * 4];
            float av[4] = {a.x, a.y, a.z, a.w};
            float bv[4] = {b.x, b.y, b.z, b.w};
            #pragma unroll
            for (int i = 0; i < 4; i++)
                #pragma unroll
                for (int j = 0; j < 4; j++) acc[i][j] += av[i] * bv[j];
        }
    }
    float* dst = outp + (size_t)blockIdx.y * M * 64;
    #pragma unroll
    for (int i = 0; i < 4; i++)
        #pragma unroll
        for (int j = 0; j < 4; j++)
            dst[(size_t)(mBase + tmq * 4 + i) * 64 + tnq * 4 + j] = acc[i][j];
}

// ============ GRU gates: reduce split-K partials + bias + gate math ============
__global__ void gru_gates(const float* __restrict__ gip, const float* __restrict__ ghp,
                          const float* __restrict__ b_ih, const float* __restrict__ b_hh,
                          const float* __restrict__ h0,
                          float* __restrict__ gh, float* __restrict__ gs,
                          float* __restrict__ dhid)
{
    int idx = blockIdx.x * 256 + threadIdx.x;   // 32768 = B*H
    int b = idx & 63, j = idx >> 6;
    float ir = b_ih[j], iz = b_ih[512 + j], in_ = b_ih[1024 + j];
    float hr = b_hh[j], hz = b_hh[512 + j], hn = b_hh[1024 + j];
    #pragma unroll
    for (int s = 0; s < 4; s++) {
        const float* gi = gip + s * 98304;
        const float* gq = ghp + s * 98304;
        ir += gi[j * 64 + b];  iz += gi[(512 + j) * 64 + b];  in_ += gi[(1024 + j) * 64 + b];
        hr += gq[j * 64 + b];  hz += gq[(512 + j) * 64 + b];  hn += gq[(1024 + j) * 64 + b];
    }
    float r = 1.f / (1.f + expf(-(ir + hr)));
    float z = 1.f / (1.f + expf(-(iz + hz)));
    float n = tanhf(in_ + r * hn);
    float h = (1.f - z) * n + z * h0[b * 512 + j];
    gh[b * 512 + j] = h;
    gs[b * 1024 + j] = h;
    dhid[b * 512 + j] = h;
}

__global__ void softmax_col(const float* __restrict__ sp, float* __restrict__ attn,
                            float* __restrict__ dattn)
{
    int b = blockIdx.x, tid = threadIdx.x;
    __shared__ float sv[SS];
    __shared__ float rb[8];
    __shared__ float smax, ssum;
    float mx = -3.4e38f;
    for (int s = tid; s < SS; s += 256) {
        float xv = 0.f;
        #pragma unroll
        for (int q = 0; q < 8; q++) xv += sp[q * (SS * BB) + s * BB + b];
        sv[s] = xv;
        mx = fmaxf(mx, xv);
    }
    #pragma unroll
    for (int o = 16; o; o >>= 1) mx = fmaxf(mx, __shfl_xor_sync(0xffffffffu, mx, o));
    if ((tid & 31) == 0) rb[tid >> 5] = mx;
    __syncthreads();
    if (tid == 0) {
        float m2 = rb[0];
        #pragma unroll
        for (int i = 1; i < 8; i++) m2 = fmaxf(m2, rb[i]);
        smax = m2;
    }
    __syncthreads();
    float sum = 0.f;
    for (int s = tid; s < SS; s += 256) {
        float e = expf(sv[s] - smax);
        sv[s] = e;
        sum += e;
    }
    #pragma unroll
    for (int o = 16; o; o >>= 1) sum += __shfl_xor_sync(0xffffffffu, sum, o);
    if ((tid & 31) == 0) rb[tid >> 5] = sum;
    __syncthreads();
    if (tid == 0) {
        float t = 0.f;
        #pragma unroll
        for (int i = 0; i < 8; i++) t += rb[i];
        ssum = t;
    }
    __syncthreads();
    float inv = 1.f / ssum;
    for (int s = tid; s < SS; s += 256) {
        float a = sv[s] * inv;
        attn[s * BB + b] = a;
        dattn[s * BB + b] = a;
    }
}

__global__ void context_k(const float* __restrict__ attn, const float* __restrict__ enc,
                          float* __restrict__ gs)
{
    int b = blockIdx.x;
    int h = blockIdx.y * 128 + threadIdx.x;
    __shared__ float at[SS];
    for (int s = threadIdx.x; s < SS; s += 128) at[s] = attn[s * BB + b];
    __syncthreads();
    float acc = 0.f;
    const float* p = enc + (size_t)b * 512 + h;
    #pragma unroll 8
    for (int s = 0; s < SS; s++) acc += at[s] * p[(size_t)s * (BB * HH)];
    gs[b * 1024 + 512 + h] = acc;
}

__global__ void pgen_k(const float* __restrict__ gs, const float* __restrict__ x,
                       const float* __restrict__ pWh, const float* __restrict__ pWs,
                       const float* __restrict__ pWx, const float* __restrict__ pWx_b,
                       float* __restrict__ gp, float* __restrict__ dp)
{
    int b = blockIdx.x, tid = threadIdx.x;
    __shared__ float rb[4];
    float a = 0.f;
    for (int j = tid; j < 512; j += 128) {
        a += gs[b * 1024 + 512 + j] * pWh[j]
           + gs[b * 1024 + j] * pWs[j]
           + x[b * 512 + j] * pWx[j];
    }
    #pragma unroll
    for (int o = 16; o; o >>= 1) a += __shfl_xor_sync(0xffffffffu, a, o);
    if ((tid & 31) == 0) rb[tid >> 5] = a;
    __syncthreads();
    if (tid == 0) {
        float t = rb[0] + rb[1] + rb[2] + rb[3];
        float p = 1.f / (1.f + expf(-(t + pWx_b[0])));
        gp[b] = p; dp[b] = p;
    }
}

__global__ void oov_k(const float* __restrict__ attn, const int* __restrict__ mask,
                      const float* __restrict__ gp, float* __restrict__ dout)
{
    int idx = blockIdx.x * 256 + threadIdx.x;
    if (idx >= SS * BB) return;
    int s = idx >> 6, b = idx & 63;
    dout[(size_t)b * VS + VV + s] = (1.f - gp[b]) * attn[idx] * (float)mask[idx];
}

extern "C" void kernel_launch(void* const* d_in, const int* in_sizes, int n_in,
                              void* d_out, int out_size)
{
    const float* x      = (const float*)d_in[0];
    const float* enc    = (const float*)d_in[1];
    const int*   mask   = (const int*)d_in[2];
    const float* h0     = (const float*)d_in[3];
    const float* W_ih   = (const float*)d_in[4];
    const float* W_hh   = (const float*)d_in[5];
    const float* b_ih   = (const float*)d_in[6];
    const float* b_hh   = (const float*)d_in[7];
    const float* out_W  = (const float*)d_in[8];
    const float* out_b  = (const float*)d_in[9];
    const float* v      = (const float*)d_in[10];
    const float* Wh     = (const float*)d_in[11];
    const float* Ws     = (const float*)d_in[12];
    const float* b_attn = (const float*)d_in[13];
    const float* pWh    = (const float*)d_in[14];
    const float* pWs    = (const float*)d_in[15];
    const float* pWx    = (const float*)d_in[16];
    const float* pWx_b  = (const float*)d_in[17];
    float* out = (float*)d_out;

    float *gip, *ghp, *x2p, *hb, *spart, *attn, *gs, *pb;
    cudaGetSymbolAddress((void**)&gip,   g_gip);
    cudaGetSymbolAddress((void**)&ghp,   g_ghp);
    cudaGetSymbolAddress((void**)&x2p,   g_x2p);
    cudaGetSymbolAddress((void**)&hb,    g_h);
    cudaGetSymbolAddress((void**)&spart, g_spart);
    cudaGetSymbolAddress((void**)&attn,  g_attn);
    cudaGetSymbolAddress((void**)&gs,    g_gs);
    cudaGetSymbolAddress((void**)&pb,    g_p);

    float* dout  = out;
    float* dhid  = out + (size_t)BB * VS;
    float* dp    = dhid + (size_t)BB * HH;
    float* dattn = dp + BB;

    small_gemm<false><<<dim3(24, 4), 256>>>(W_ih, x, gip, 1536);
    small_gemm<false><<<dim3(24, 4), 256>>>(W_hh, h0, ghp, 1536);
    gru_gates<<<128, 256>>>(gip, ghp, b_ih, b_hh, h0, hb, gs, dhid);
    small_gemm<true><<<dim3(8, 4), 256>>>(Ws, hb, x2p, 512);
    gemm_nt<1, true><<<dim3(200, 8), 128>>>(enc, Wh, nullptr, spart,
                                            SS * BB, 512, 512, x2p, v, nullptr, b_attn);
    softmax_col<<<64, 256>>>(spart, attn, dattn);
    context_k<<<dim3(64, 4), 128>>>(attn, enc, gs);
    pgen_k<<<64, 128>>>(gs, x, pWh, pWs, pWx, pWx_b, pb, dp);
    gemm_nt<2, false><<<dim3(391, 1), 128>>>(out_W, gs, out_b, dout,
                                             VV, 2 * HH, 0, nullptr, nullptr, pb, nullptr);
    oov_k<<<100, 256>>>(attn, mask, pb, dout);
}